// round 13
// baseline (speedup 1.0000x reference)
#include <cuda_runtime.h>
#include <cuda_bf16.h>
#include <mma.h>
#include <cstdint>
#include <math.h>

using namespace nvcuda;

#define BB 256
#define TT 512
#define VV 10
#define EE 10
#define HH 1024
#define CC 10
#define KW 1034
#define NCTA 256
#define NTHR 256

// ---------------- device scratch ----------------
__device__ float g_h[BB * HH];
__device__ float g_z[BB * HH];
__device__ __nv_bfloat16 g_ha[2][BB * HH];    // h hi/lo   (phase1 A)
__device__ __nv_bfloat16 g_hra[2][BB * HH];   // h*r hi/lo (phase2 A)
__device__ __nv_bfloat16 g_w[3][2][HH * HH];  // weight splits, K-major [j*HH+k]
__device__ float g_pre[3][VV][HH];            // x-path tables
__device__ unsigned g_count;
__device__ volatile unsigned g_phase;

// smem per CTA: [0,1024) pad; 2 stages.
// phase1 K=64 sub-block: Ahi 64x144 (9216) | Alo 9216 | Bhi 32x144 (4608) | Blo 4608 = 27648
// phase1 K=128 chunk = 2 subs = 55296. 2 stages = 110592.
// phase2 K=64 sub-block: Ahi 32x144 (4608) | Alo | Bhi | Blo = 18432; chunk = 36864.
// C partials alias stage 0 (phase1 C = 4*64*36*4 = 36864; phase2 C = 18432).
#define P1SUB  27648
#define P1CH   55296
#define P2SUB  18432
#define P2CH   36864
#define LDMAB  72
#define LDMC   36
#define SMEM_TOTAL (1024 + 2 * P1CH)

typedef wmma::fragment<wmma::accumulator, 16, 16, 16, float> FragC;
typedef wmma::fragment<wmma::matrix_a, 16, 16, 16, __nv_bfloat16, wmma::row_major> FragA;
typedef wmma::fragment<wmma::matrix_b, 16, 16, 16, __nv_bfloat16, wmma::col_major> FragB;

// ---------------- math ----------------
static __device__ __forceinline__ float sigf(float v) {
    return __fdividef(1.f, 1.f + __expf(-v));
}
static __device__ __forceinline__ float fast_tanh(float v) {
    v = fminf(fmaxf(v, -15.f), 15.f);
    float e = __expf(-2.f * v);
    return __fdividef(1.f - e, 1.f + e);
}
static __device__ __forceinline__ uint32_t pack_bf2(float a, float b) {
    __nv_bfloat16 x = __float2bfloat16(a), y = __float2bfloat16(b);
    return ((uint32_t)__bfloat16_as_ushort(y) << 16) | (uint32_t)__bfloat16_as_ushort(x);
}
static __device__ __forceinline__ uint32_t smem_u32(const void* p) {
    uint32_t a;
    asm("{ .reg .u64 t; cvta.to.shared.u64 t, %1; cvt.u32.u64 %0, t; }" : "=r"(a) : "l"(p));
    return a;
}
#define CP16(dst, src) \
    asm volatile("cp.async.cg.shared.global [%0], [%1], 16;" :: "r"(dst), "l"(src))
#define CPCOMMIT() asm volatile("cp.async.commit_group;" ::: "memory")
#define CPWAIT0()  asm volatile("cp.async.wait_group 0;" ::: "memory")

// ---------------- grid barrier (PROVEN atomic version) ----------------
static __device__ __forceinline__ void grid_sync() {
    __syncthreads();
    if (threadIdx.x == 0) {
        __threadfence();
        unsigned ph = g_phase;
        if (atomicAdd(&g_count, 1u) == gridDim.x - 1u) {
            g_count = 0u;
            __threadfence();
            g_phase = ph + 1u;
        } else {
            while (g_phase == ph) { __nanosleep(32); }
        }
        __threadfence();
    }
    __syncthreads();
}

// ---------------- precompute ----------------
__global__ void precompute_kernel(const float* __restrict__ embed,
                                  const float* __restrict__ Wz,
                                  const float* __restrict__ Wr,
                                  const float* __restrict__ Wc) {
    long idx = (long)blockIdx.x * 256 + threadIdx.x;
    const long NSPLIT = 3L * HH * HH;
    if (idx < NSPLIT) {
        int g = (int)(idx / (HH * HH));
        int rem = (int)(idx % (HH * HH));
        int j = rem / HH, k = rem % HH;
        const float* Wg = (g == 0) ? Wz : (g == 1) ? Wr : Wc;
        float w = Wg[(long)j * KW + k];
        __nv_bfloat16 hi = __float2bfloat16(w);
        g_w[g][0][rem] = hi;
        g_w[g][1][rem] = __float2bfloat16(w - __bfloat162float(hi));
    } else {
        long r = idx - NSPLIT;
        if (r < 3L * VV * HH) {
            int g = (int)(r / (VV * HH));
            int rem = (int)(r % (VV * HH));
            int v = rem / HH, j = rem % HH;
            const float* Wg = (g == 0) ? Wz : (g == 1) ? Wr : Wc;
            float s = 0.f;
#pragma unroll
            for (int e = 0; e < EE; ++e)
                s += embed[v * EE + e] * Wg[(long)j * KW + HH + e];
            g_pre[g][v][j] = s;
        }
    }
}

// ---------------- cp.async staging (256 threads) ----------------
// phase1 A: 2 mats x 64 rows x 8 cols(16B) -> 2 ops/thread/mat
static __device__ __forceinline__ void sub1_A(
    uint32_t sbuf, const __nv_bfloat16* __restrict__ ahi,
    const __nv_bfloat16* __restrict__ alo, int k0, int tid) {
#pragma unroll
    for (int mat = 0; mat < 2; ++mat) {
        const __nv_bfloat16* base = mat ? alo : ahi;
#pragma unroll
        for (int i = 0; i < 2; ++i) {
            int u = tid + (i << 8);
            int row = u >> 3, c = u & 7;
            CP16(sbuf + mat * 9216 + row * 144 + (c << 4),
                 base + (long)row * HH + k0 + (c << 3));
        }
    }
}
// phase1 B: 2 mats x 32 rows x 8 -> 1 op/thread/mat
static __device__ __forceinline__ void sub1_B(
    uint32_t sbuf, const __nv_bfloat16* __restrict__ bhi,
    const __nv_bfloat16* __restrict__ blo, int k0, int tid) {
#pragma unroll
    for (int mat = 0; mat < 2; ++mat) {
        const __nv_bfloat16* base = mat ? blo : bhi;
        int row = tid >> 3, c = tid & 7;
        CP16(sbuf + 18432 + mat * 4608 + row * 144 + (c << 4),
             base + (long)row * HH + k0 + (c << 3));
    }
}
static __device__ __forceinline__ void chunk1_A(
    uint32_t sbuf, const __nv_bfloat16* ahi, const __nv_bfloat16* alo, int k0, int tid) {
    sub1_A(sbuf, ahi, alo, k0, tid);
    sub1_A(sbuf + P1SUB, ahi, alo, k0 + 64, tid);
}
static __device__ __forceinline__ void chunk1_B(
    uint32_t sbuf, const __nv_bfloat16* bhi, const __nv_bfloat16* blo, int k0, int tid) {
    sub1_B(sbuf, bhi, blo, k0, tid);
    sub1_B(sbuf + P1SUB, bhi, blo, k0 + 64, tid);
}
// phase2 A: 2 mats x 32 rows -> 1 op/thread/mat
static __device__ __forceinline__ void sub2_A(
    uint32_t sbuf, const __nv_bfloat16* __restrict__ ahi,
    const __nv_bfloat16* __restrict__ alo, int k0, int tid) {
#pragma unroll
    for (int mat = 0; mat < 2; ++mat) {
        const __nv_bfloat16* base = mat ? alo : ahi;
        int row = tid >> 3, c = tid & 7;
        CP16(sbuf + mat * 4608 + row * 144 + (c << 4),
             base + (long)row * HH + k0 + (c << 3));
    }
}
static __device__ __forceinline__ void sub2_B(
    uint32_t sbuf, const __nv_bfloat16* __restrict__ bhi,
    const __nv_bfloat16* __restrict__ blo, int k0, int tid) {
#pragma unroll
    for (int mat = 0; mat < 2; ++mat) {
        const __nv_bfloat16* base = mat ? blo : bhi;
        int row = tid >> 3, c = tid & 7;
        CP16(sbuf + 9216 + mat * 4608 + row * 144 + (c << 4),
             base + (long)row * HH + k0 + (c << 3));
    }
}
static __device__ __forceinline__ void chunk2_A(
    uint32_t sbuf, const __nv_bfloat16* ahi, const __nv_bfloat16* alo, int k0, int tid) {
    sub2_A(sbuf, ahi, alo, k0, tid);
    sub2_A(sbuf + P2SUB, ahi, alo, k0 + 64, tid);
}
static __device__ __forceinline__ void chunk2_B(
    uint32_t sbuf, const __nv_bfloat16* bhi, const __nv_bfloat16* blo, int k0, int tid) {
    sub2_B(sbuf, bhi, blo, k0, tid);
    sub2_B(sbuf + P2SUB, bhi, blo, k0 + 64, tid);
}
// pre-barrier B prefetch for chunks 0,1 (ONE commit group)
static __device__ __forceinline__ void preB1(
    uint32_t sbase, const __nv_bfloat16* bhi, const __nv_bfloat16* blo, int tid) {
#pragma unroll
    for (int ch = 0; ch < 2; ++ch)
        chunk1_B(sbase + 1024 + ch * P1CH, bhi, blo, ch * 128, tid);
    CPCOMMIT();
}
static __device__ __forceinline__ void preB2(
    uint32_t sbase, const __nv_bfloat16* bhi, const __nv_bfloat16* blo, int tid) {
#pragma unroll
    for (int ch = 0; ch < 2; ++ch)
        chunk2_B(sbase + 1024 + ch * P2CH, bhi, blo, ch * 128, tid);
    CPCOMMIT();
}

// ---------------- phase1 compute: warp tile 32x32 of 64x32, one kstep ----
static __device__ __forceinline__ void compute_p1(
    const char* buf, int grp, int wm,
    FragC& c00, FragC& c01, FragC& c10, FragC& c11) {
    const __nv_bfloat16* Ah = reinterpret_cast<const __nv_bfloat16*>(buf);
    const __nv_bfloat16* Al = reinterpret_cast<const __nv_bfloat16*>(buf + 9216);
    const __nv_bfloat16* Bh = reinterpret_cast<const __nv_bfloat16*>(buf + 18432);
    const __nv_bfloat16* Bl = reinterpret_cast<const __nv_bfloat16*>(buf + 23040);
    const int ko = grp << 4;
    FragA ah0, ah1, al0, al1;
    FragB bh0, bh1, bl0, bl1;
    wmma::load_matrix_sync(ah0, Ah + (wm * 32) * LDMAB + ko, LDMAB);
    wmma::load_matrix_sync(ah1, Ah + (wm * 32 + 16) * LDMAB + ko, LDMAB);
    wmma::load_matrix_sync(bh0, Bh + ko, LDMAB);
    wmma::load_matrix_sync(bh1, Bh + 16 * LDMAB + ko, LDMAB);
    wmma::mma_sync(c00, ah0, bh0, c00);
    wmma::mma_sync(c01, ah0, bh1, c01);
    wmma::mma_sync(c10, ah1, bh0, c10);
    wmma::mma_sync(c11, ah1, bh1, c11);
    wmma::load_matrix_sync(bl0, Bl + ko, LDMAB);
    wmma::load_matrix_sync(bl1, Bl + 16 * LDMAB + ko, LDMAB);
    wmma::mma_sync(c00, ah0, bl0, c00);
    wmma::mma_sync(c01, ah0, bl1, c01);
    wmma::mma_sync(c10, ah1, bl0, c10);
    wmma::mma_sync(c11, ah1, bl1, c11);
    wmma::load_matrix_sync(al0, Al + (wm * 32) * LDMAB + ko, LDMAB);
    wmma::load_matrix_sync(al1, Al + (wm * 32 + 16) * LDMAB + ko, LDMAB);
    wmma::mma_sync(c00, al0, bh0, c00);
    wmma::mma_sync(c01, al0, bh1, c01);
    wmma::mma_sync(c10, al1, bh0, c10);
    wmma::mma_sync(c11, al1, bh1, c11);
}

// ---------------- phase2 compute: warp tile 16x32 of 32x32, one kstep ----
static __device__ __forceinline__ void compute_p2(
    const char* buf, int grp, int wm, FragC& c0, FragC& c1) {
    const __nv_bfloat16* Ah = reinterpret_cast<const __nv_bfloat16*>(buf);
    const __nv_bfloat16* Al = reinterpret_cast<const __nv_bfloat16*>(buf + 4608);
    const __nv_bfloat16* Bh = reinterpret_cast<const __nv_bfloat16*>(buf + 9216);
    const __nv_bfloat16* Bl = reinterpret_cast<const __nv_bfloat16*>(buf + 13824);
    const int ko = grp << 4;
    FragA ah, al;
    FragB bh0, bh1, bl0, bl1;
    wmma::load_matrix_sync(ah, Ah + (wm * 16) * LDMAB + ko, LDMAB);
    wmma::load_matrix_sync(bh0, Bh + ko, LDMAB);
    wmma::load_matrix_sync(bh1, Bh + 16 * LDMAB + ko, LDMAB);
    wmma::mma_sync(c0, ah, bh0, c0);
    wmma::mma_sync(c1, ah, bh1, c1);
    wmma::load_matrix_sync(bl0, Bl + ko, LDMAB);
    wmma::load_matrix_sync(bl1, Bl + 16 * LDMAB + ko, LDMAB);
    wmma::mma_sync(c0, ah, bl0, c0);
    wmma::mma_sync(c1, ah, bl1, c1);
    wmma::load_matrix_sync(al, Al + (wm * 16) * LDMAB + ko, LDMAB);
    wmma::mma_sync(c0, al, bh0, c0);
    wmma::mma_sync(c1, al, bh1, c1);
}

// ---------------- phase1 GEMM: 64x32x1024, 2-stage, issue-after-sync -----
static __device__ void run_gemm1(
    char* sm, uint32_t sbase,
    const __nv_bfloat16* __restrict__ ahi, const __nv_bfloat16* __restrict__ alo,
    const __nv_bfloat16* __restrict__ bhi, const __nv_bfloat16* __restrict__ blo,
    int tid, int grp, int wm) {
    FragC c00, c01, c10, c11;
    wmma::fill_fragment(c00, 0.f);
    wmma::fill_fragment(c01, 0.f);
    wmma::fill_fragment(c10, 0.f);
    wmma::fill_fragment(c11, 0.f);

    chunk1_A(sbase + 1024, ahi, alo, 0, tid);
    CPCOMMIT();

#pragma unroll 1
    for (int c = 0; c < 8; ++c) {
        CPWAIT0();
        __syncthreads();   // all warps done with stage (c+1)&1's previous chunk
        if (c < 7) {
            uint32_t sb = sbase + 1024 + ((c + 1) & 1) * P1CH;
            chunk1_A(sb, ahi, alo, (c + 1) * 128, tid);
            if (c + 1 >= 2) chunk1_B(sb, bhi, blo, (c + 1) * 128, tid);
            CPCOMMIT();
        }
        const char* buf = sm + 1024 + (c & 1) * P1CH;
        compute_p1(buf, grp, wm, c00, c01, c10, c11);
        compute_p1(buf + P1SUB, grp, wm, c00, c01, c10, c11);
    }
    // C partials alias stage0 (last reader = chunk 6, synced at c=7)
    float* sCg = reinterpret_cast<float*>(sm + 1024) + grp * (64 * LDMC);
    wmma::store_matrix_sync(sCg + (wm * 32) * LDMC, c00, LDMC, wmma::mem_row_major);
    wmma::store_matrix_sync(sCg + (wm * 32) * LDMC + 16, c01, LDMC, wmma::mem_row_major);
    wmma::store_matrix_sync(sCg + (wm * 32 + 16) * LDMC, c10, LDMC, wmma::mem_row_major);
    wmma::store_matrix_sync(sCg + (wm * 32 + 16) * LDMC + 16, c11, LDMC, wmma::mem_row_major);
    __syncthreads();
}

// ---------------- phase2 GEMM: 32x32x1024, 2-stage, issue-after-sync -----
static __device__ void run_gemm2(
    char* sm, uint32_t sbase,
    const __nv_bfloat16* __restrict__ ahi, const __nv_bfloat16* __restrict__ alo,
    const __nv_bfloat16* __restrict__ bhi, const __nv_bfloat16* __restrict__ blo,
    int tid, int grp, int wm) {
    FragC c0, c1;
    wmma::fill_fragment(c0, 0.f);
    wmma::fill_fragment(c1, 0.f);

    chunk2_A(sbase + 1024, ahi, alo, 0, tid);
    CPCOMMIT();

#pragma unroll 1
    for (int c = 0; c < 8; ++c) {
        CPWAIT0();
        __syncthreads();
        if (c < 7) {
            uint32_t sb = sbase + 1024 + ((c + 1) & 1) * P2CH;
            chunk2_A(sb, ahi, alo, (c + 1) * 128, tid);
            if (c + 1 >= 2) chunk2_B(sb, bhi, blo, (c + 1) * 128, tid);
            CPCOMMIT();
        }
        const char* buf = sm + 1024 + (c & 1) * P2CH;
        compute_p2(buf, grp, wm, c0, c1);
        compute_p2(buf + P2SUB, grp, wm, c0, c1);
    }
    float* sCg = reinterpret_cast<float*>(sm + 1024) + grp * (32 * LDMC);
    wmma::store_matrix_sync(sCg + (wm * 16) * LDMC, c0, LDMC, wmma::mem_row_major);
    wmma::store_matrix_sync(sCg + (wm * 16) * LDMC + 16, c1, LDMC, wmma::mem_row_major);
    __syncthreads();
}

// ---------------- main persistent kernel (2 CTAs/SM) ----------------
__global__ void __launch_bounds__(NTHR, 2)
gru_tc(const int* __restrict__ x,
       const float* __restrict__ Wph,
       const float* __restrict__ bp,
       float* __restrict__ out) {
    extern __shared__ __align__(16) char smem[];
    const uint32_t sbase = smem_u32(smem);
    const int tid = threadIdx.x;
    const int wid = tid >> 5;
    const int lane = tid & 31;
    const int cta = blockIdx.x;
    const int grp = wid >> 1;            // K group 0..3
    const int wm = wid & 1;              // M half within tile

    for (int i = cta * NTHR + tid; i < BB * HH; i += NCTA * NTHR) {
        g_h[i] = 0.f;
        g_ha[0][i] = __float2bfloat16(0.f);
        g_ha[1][i] = __float2bfloat16(0.f);
    }

    // phase1: 256 tiles = 4 M-strips(64) x (32 z + 32 r) N-tiles(32)
    const int p1_bm = (cta & 3) << 6;
    const int p1_nt = cta >> 2;          // 0..63
    const int p1_gate = p1_nt >> 5;
    const int p1_jb = (p1_nt & 31) << 5;
    // phase2: 256 tiles = 8 M-strips(32) x 32 N-tiles(32)
    const int p2_bm = (cta & 7) << 5;
    const int p2_jb = (cta >> 3) << 5;

    const __nv_bfloat16* w1hi = &g_w[p1_gate][0][p1_jb * HH];
    const __nv_bfloat16* w1lo = &g_w[p1_gate][1][p1_jb * HH];
    const __nv_bfloat16* w2hi = &g_w[2][0][p2_jb * HH];
    const __nv_bfloat16* w2lo = &g_w[2][1][p2_jb * HH];

    preB1(sbase, w1hi, w1lo, tid);   // fill during init barrier
    grid_sync();

    const float* sC = reinterpret_cast<const float*>(smem + 1024);

    for (int t = 0; t < TT; ++t) {
        // ============ phase 1: z / r gates ============
        run_gemm1(smem, sbase,
                  &g_ha[0][p1_bm * HH], &g_ha[1][p1_bm * HH],
                  w1hi, w1lo, tid, grp, wm);
        {
            const int er = tid >> 2;              // 0..63
            const int ecb = (tid & 3) << 3;       // 8 cols
            const float* cr = sC + er * LDMC + ecb;
            float v[8];
            {
                float4 a0 = *reinterpret_cast<const float4*>(cr);
                float4 a1 = *reinterpret_cast<const float4*>(cr + 4);
#pragma unroll
                for (int g = 1; g < 4; ++g) {
                    const float* crg = cr + g * (64 * LDMC);
                    float4 b0 = *reinterpret_cast<const float4*>(crg);
                    float4 b1 = *reinterpret_cast<const float4*>(crg + 4);
                    a0.x += b0.x; a0.y += b0.y; a0.z += b0.z; a0.w += b0.w;
                    a1.x += b1.x; a1.y += b1.y; a1.z += b1.z; a1.w += b1.w;
                }
                v[0] = a0.x; v[1] = a0.y; v[2] = a0.z; v[3] = a0.w;
                v[4] = a1.x; v[5] = a1.y; v[6] = a1.z; v[7] = a1.w;
            }
            const int b = p1_bm + er;
            const int tok = x[b * TT + t];
            const float* __restrict__ pre = &g_pre[p1_gate][tok][p1_jb + ecb];
            if (p1_gate == 0) {
                float* __restrict__ dst = &g_z[b * HH + p1_jb + ecb];
#pragma unroll
                for (int q = 0; q < 2; ++q) {
                    float4 p = *reinterpret_cast<const float4*>(pre + q * 4);
                    float4 o;
                    o.x = sigf(v[q * 4 + 0] + p.x);
                    o.y = sigf(v[q * 4 + 1] + p.y);
                    o.z = sigf(v[q * 4 + 2] + p.z);
                    o.w = sigf(v[q * 4 + 3] + p.w);
                    *reinterpret_cast<float4*>(dst + q * 4) = o;
                }
            } else {
                const float* __restrict__ hrow = &g_h[b * HH + p1_jb + ecb];
                float hr[8];
#pragma unroll
                for (int q = 0; q < 2; ++q) {
                    float4 p = *reinterpret_cast<const float4*>(pre + q * 4);
                    float4 h4 = *reinterpret_cast<const float4*>(hrow + q * 4);
                    hr[q * 4 + 0] = sigf(v[q * 4 + 0] + p.x) * h4.x;
                    hr[q * 4 + 1] = sigf(v[q * 4 + 1] + p.y) * h4.y;
                    hr[q * 4 + 2] = sigf(v[q * 4 + 2] + p.z) * h4.z;
                    hr[q * 4 + 3] = sigf(v[q * 4 + 3] + p.w) * h4.w;
                }
                uint32_t phi[4], plo[4];
#pragma unroll
                for (int q = 0; q < 4; ++q) {
                    float a = hr[2 * q], bx = hr[2 * q + 1];
                    float ea = a - __bfloat162float(__float2bfloat16(a));
                    float eb = bx - __bfloat162float(__float2bfloat16(bx));
                    phi[q] = pack_bf2(a, bx);
                    plo[q] = pack_bf2(ea, eb);
                }
                *reinterpret_cast<uint4*>(&g_hra[0][b * HH + p1_jb + ecb]) =
                    make_uint4(phi[0], phi[1], phi[2], phi[3]);
                *reinterpret_cast<uint4*>(&g_hra[1][b * HH + p1_jb + ecb]) =
                    make_uint4(plo[0], plo[1], plo[2], plo[3]);
            }
        }
        __syncthreads();                  // epilogue C reads done before preB2 overwrite
        preB2(sbase, w2hi, w2lo, tid);    // fill during barrier wait
        grid_sync();

        // ============ phase 2: candidate + state update ============
        run_gemm2(smem, sbase,
                  &g_hra[0][p2_bm * HH], &g_hra[1][p2_bm * HH],
                  w2hi, w2lo, tid, grp, wm);
        {
            const int er = tid >> 3;              // 0..31
            const int ecb = (tid & 7) << 2;       // 4 cols
            const float* cr = sC + er * LDMC + ecb;
            float4 v = *reinterpret_cast<const float4*>(cr);
#pragma unroll
            for (int g = 1; g < 4; ++g) {
                float4 bq = *reinterpret_cast<const float4*>(cr + g * (32 * LDMC));
                v.x += bq.x; v.y += bq.y; v.z += bq.z; v.w += bq.w;
            }
            const int b = p2_bm + er;
            const int tok = x[b * TT + t];
            const float* __restrict__ pre = &g_pre[2][tok][p2_jb + ecb];
            float* __restrict__ hrow = &g_h[b * HH + p2_jb + ecb];
            const float* __restrict__ zrow = &g_z[b * HH + p2_jb + ecb];
            float4 p = *reinterpret_cast<const float4*>(pre);
            float4 h4 = *reinterpret_cast<const float4*>(hrow);
            float4 z4 = *reinterpret_cast<const float4*>(zrow);
            float hn[4];
            hn[0] = h4.x + z4.x * (fast_tanh(v.x + p.x) - h4.x);
            hn[1] = h4.y + z4.y * (fast_tanh(v.y + p.y) - h4.y);
            hn[2] = h4.z + z4.z * (fast_tanh(v.z + p.z) - h4.z);
            hn[3] = h4.w + z4.w * (fast_tanh(v.w + p.w) - h4.w);
            *reinterpret_cast<float4*>(hrow) = make_float4(hn[0], hn[1], hn[2], hn[3]);
            uint32_t phi[2], plo[2];
#pragma unroll
            for (int q = 0; q < 2; ++q) {
                float a = hn[2 * q], bx = hn[2 * q + 1];
                float ea = a - __bfloat162float(__float2bfloat16(a));
                float eb = bx - __bfloat162float(__float2bfloat16(bx));
                phi[q] = pack_bf2(a, bx);
                plo[q] = pack_bf2(ea, eb);
            }
            *reinterpret_cast<uint2*>(&g_ha[0][b * HH + p2_jb + ecb]) = make_uint2(phi[0], phi[1]);
            *reinterpret_cast<uint2*>(&g_ha[1][b * HH + p2_jb + ecb]) = make_uint2(plo[0], plo[1]);
        }
        __syncthreads();
        preB1(sbase, w1hi, w1lo, tid);    // for next t (harmless at t=TT-1)
        grid_sync();
    }

    CPWAIT0();   // drain stray prefetch

    // ============ output projection ============
    const int warpId = (cta << 3) + wid;
    const int nWarps = NCTA << 3;
    for (int oc = warpId; oc < BB * CC; oc += nWarps) {
        const int b = oc / CC;
        const int c = oc - b * CC;
        const float* hrow = &g_h[b * HH];
        const float* wrow = &Wph[c * HH];
        float s = 0.f;
        for (int j = lane; j < HH; j += 32)
            s += hrow[j] * wrow[j];
#pragma unroll
        for (int off = 16; off; off >>= 1)
            s += __shfl_xor_sync(0xffffffffu, s, off);
        if (lane == 0) out[oc] = s + bp[c];
    }
}

// ---------------- launch ----------------
extern "C" void kernel_launch(void* const* d_in, const int* in_sizes, int n_in,
                              void* d_out, int out_size) {
    const int*   x     = (const int*)d_in[0];
    const float* embed = (const float*)d_in[1];
    const float* Wz    = (const float*)d_in[2];
    const float* Wr    = (const float*)d_in[3];
    const float* Wc    = (const float*)d_in[4];
    const float* Wph   = (const float*)d_in[5];
    const float* bp    = (const float*)d_in[6];
    float* out = (float*)d_out;

    cudaFuncSetAttribute(gru_tc, cudaFuncAttributeMaxDynamicSharedMemorySize, SMEM_TOTAL);

    const long total = 3L * HH * HH + 3L * VV * HH;
    precompute_kernel<<<(unsigned)((total + 255) / 256), 256>>>(embed, Wz, Wr, Wc);
    gru_tc<<<NCTA, NTHR, SMEM_TOTAL>>>(x, Wph, bp, out);
}

// round 14
// speedup vs baseline: 1.0260x; 1.0260x over previous
#include <cuda_runtime.h>
#include <cuda_bf16.h>
#include <mma.h>
#include <cstdint>
#include <math.h>

using namespace nvcuda;

#define BB 256
#define TT 512
#define VV 10
#define EE 10
#define HH 1024
#define CC 10
#define KW 1034
#define NCTA 128
#define NTHR 512

// ---------------- device scratch ----------------
__device__ float g_h[BB * HH];
__device__ float g_z[BB * HH];
__device__ __nv_bfloat16 g_ha[2][BB * HH];    // h hi/lo   (phase1 A)
__device__ __nv_bfloat16 g_hra[2][BB * HH];   // h*r hi/lo (phase2 A)
__device__ __nv_bfloat16 g_w[3][2][HH * HH];  // weight splits, K-major [j*HH+k]
__device__ float g_pre[3][VV][HH];            // x-path tables
__device__ unsigned g_count;
__device__ volatile unsigned g_phase;

// smem: [0,1024) pad; 3 stages of K=128 chunks at 1024 + s*P1CH.
// C partials ALIAS stage 0 (written only after mainloop, read in epilogue).
#define P1SUB  36864
#define P1CH   73728
#define P2SUB  27648
#define P2CH   55296
#define MATSZ  9216
#define LDMAB  72
#define LDMC   68
#define CBASE  1024
#define SMEM_TOTAL (1024 + 3 * P1CH)

typedef wmma::fragment<wmma::accumulator, 16, 16, 16, float> FragC;
typedef wmma::fragment<wmma::matrix_a, 16, 16, 16, __nv_bfloat16, wmma::row_major> FragA;
typedef wmma::fragment<wmma::matrix_b, 16, 16, 16, __nv_bfloat16, wmma::col_major> FragB;

// ---------------- math ----------------
static __device__ __forceinline__ float sigf(float v) {
    return __fdividef(1.f, 1.f + __expf(-v));
}
static __device__ __forceinline__ float fast_tanh(float v) {
    v = fminf(fmaxf(v, -15.f), 15.f);
    float e = __expf(-2.f * v);
    return __fdividef(1.f - e, 1.f + e);
}
static __device__ __forceinline__ uint32_t pack_bf2(float a, float b) {
    __nv_bfloat16 x = __float2bfloat16(a), y = __float2bfloat16(b);
    return ((uint32_t)__bfloat16_as_ushort(y) << 16) | (uint32_t)__bfloat16_as_ushort(x);
}
static __device__ __forceinline__ uint32_t smem_u32(const void* p) {
    uint32_t a;
    asm("{ .reg .u64 t; cvta.to.shared.u64 t, %1; cvt.u32.u64 %0, t; }" : "=r"(a) : "l"(p));
    return a;
}
#define CP16(dst, src) \
    asm volatile("cp.async.cg.shared.global [%0], [%1], 16;" :: "r"(dst), "l"(src))
#define CPCOMMIT() asm volatile("cp.async.commit_group;" ::: "memory")

// ---------------- grid barrier (proven atomic version) ----------------
static __device__ __forceinline__ void grid_sync() {
    __syncthreads();
    if (threadIdx.x == 0) {
        __threadfence();
        unsigned ph = g_phase;
        if (atomicAdd(&g_count, 1u) == gridDim.x - 1u) {
            g_count = 0u;
            __threadfence();
            g_phase = ph + 1u;
        } else {
            while (g_phase == ph) { __nanosleep(32); }
        }
        __threadfence();
    }
    __syncthreads();
}

// ---------------- precompute ----------------
__global__ void precompute_kernel(const float* __restrict__ embed,
                                  const float* __restrict__ Wz,
                                  const float* __restrict__ Wr,
                                  const float* __restrict__ Wc) {
    long idx = (long)blockIdx.x * 256 + threadIdx.x;
    const long NSPLIT = 3L * HH * HH;
    if (idx < NSPLIT) {
        int g = (int)(idx / (HH * HH));
        int rem = (int)(idx % (HH * HH));
        int j = rem / HH, k = rem % HH;
        const float* Wg = (g == 0) ? Wz : (g == 1) ? Wr : Wc;
        float w = Wg[(long)j * KW + k];
        __nv_bfloat16 hi = __float2bfloat16(w);
        g_w[g][0][rem] = hi;
        g_w[g][1][rem] = __float2bfloat16(w - __bfloat162float(hi));
    } else {
        long r = idx - NSPLIT;
        if (r < 3L * VV * HH) {
            int g = (int)(r / (VV * HH));
            int rem = (int)(r % (VV * HH));
            int v = rem / HH, j = rem % HH;
            const float* Wg = (g == 0) ? Wz : (g == 1) ? Wr : Wc;
            float s = 0.f;
#pragma unroll
            for (int e = 0; e < EE; ++e)
                s += embed[v * EE + e] * Wg[(long)j * KW + HH + e];
            g_pre[g][v][j] = s;
        }
    }
}

// ---------------- cp.async staging pieces ----------------
static __device__ __forceinline__ void sub1_A(
    uint32_t sbuf, const __nv_bfloat16* __restrict__ ahi,
    const __nv_bfloat16* __restrict__ alo, int k0, int tid) {
#pragma unroll
    for (int i = 0; i < 2; ++i) {
        const __nv_bfloat16* base = i ? alo : ahi;
        int row = tid >> 3, c = tid & 7;
        CP16(sbuf + i * MATSZ + row * 144 + (c << 4),
             base + (long)row * HH + k0 + (c << 3));
    }
}
static __device__ __forceinline__ void sub1_B(
    uint32_t sbuf, const __nv_bfloat16* __restrict__ bhi,
    const __nv_bfloat16* __restrict__ blo, int k0, int tid) {
#pragma unroll
    for (int i = 0; i < 2; ++i) {
        const __nv_bfloat16* base = i ? blo : bhi;
        int row = tid >> 3, c = tid & 7;
        CP16(sbuf + (2 + i) * MATSZ + row * 144 + (c << 4),
             base + (long)row * HH + k0 + (c << 3));
    }
}
static __device__ __forceinline__ void chunk1_A(
    uint32_t sbuf, const __nv_bfloat16* ahi, const __nv_bfloat16* alo, int k0, int tid) {
    sub1_A(sbuf, ahi, alo, k0, tid);
    sub1_A(sbuf + P1SUB, ahi, alo, k0 + 64, tid);
}
static __device__ __forceinline__ void chunk1_B(
    uint32_t sbuf, const __nv_bfloat16* bhi, const __nv_bfloat16* blo, int k0, int tid) {
    sub1_B(sbuf, bhi, blo, k0, tid);
    sub1_B(sbuf + P1SUB, bhi, blo, k0 + 64, tid);
}
static __device__ __forceinline__ void sub2_A(
    uint32_t sbuf, const __nv_bfloat16* __restrict__ ahi,
    const __nv_bfloat16* __restrict__ alo, int k0, int tid) {
    int mat = tid >> 8, v = tid & 255;
    int row = v >> 3, c = v & 7;
    const __nv_bfloat16* base = mat ? alo : ahi;
    CP16(sbuf + mat * 4608 + row * 144 + (c << 4),
         base + (long)row * HH + k0 + (c << 3));
}
static __device__ __forceinline__ void sub2_B(
    uint32_t sbuf, const __nv_bfloat16* __restrict__ bhi,
    const __nv_bfloat16* __restrict__ blo, int k0, int tid) {
#pragma unroll
    for (int i = 0; i < 2; ++i) {
        int u = tid + (i << 9);
        int mat = u >> 9, v = u & 511;
        int row = v >> 3, c = v & 7;
        const __nv_bfloat16* base = mat ? blo : bhi;
        CP16(sbuf + 9216 + mat * MATSZ + row * 144 + (c << 4),
             base + (long)row * HH + k0 + (c << 3));
    }
}
static __device__ __forceinline__ void chunk2_A(
    uint32_t sbuf, const __nv_bfloat16* ahi, const __nv_bfloat16* alo, int k0, int tid) {
    sub2_A(sbuf, ahi, alo, k0, tid);
    sub2_A(sbuf + P2SUB, ahi, alo, k0 + 64, tid);
}
static __device__ __forceinline__ void chunk2_B(
    uint32_t sbuf, const __nv_bfloat16* bhi, const __nv_bfloat16* blo, int k0, int tid) {
    sub2_B(sbuf, bhi, blo, k0, tid);
    sub2_B(sbuf + P2SUB, bhi, blo, k0 + 64, tid);
}
static __device__ __forceinline__ void preB1(
    uint32_t sbase, const __nv_bfloat16* bhi, const __nv_bfloat16* blo, int tid) {
#pragma unroll
    for (int ch = 0; ch < 3; ++ch)
        chunk1_B(sbase + 1024 + ch * P1CH, bhi, blo, ch * 128, tid);
    CPCOMMIT();
}
static __device__ __forceinline__ void preB2(
    uint32_t sbase, const __nv_bfloat16* bhi, const __nv_bfloat16* blo, int tid) {
#pragma unroll
    for (int ch = 0; ch < 3; ++ch)
        chunk2_B(sbase + 1024 + ch * P2CH, bhi, blo, ch * 128, tid);
    CPCOMMIT();
}

// ---------------- phase1 compute: warp tile 32x32, one kstep ----------------
static __device__ __forceinline__ void compute_p1(
    const char* buf, int grp, int wm, int wn,
    FragC& c00, FragC& c01, FragC& c10, FragC& c11) {
    const __nv_bfloat16* Ah = reinterpret_cast<const __nv_bfloat16*>(buf);
    const __nv_bfloat16* Al = reinterpret_cast<const __nv_bfloat16*>(buf + MATSZ);
    const __nv_bfloat16* Bh = reinterpret_cast<const __nv_bfloat16*>(buf + 2 * MATSZ);
    const __nv_bfloat16* Bl = reinterpret_cast<const __nv_bfloat16*>(buf + 3 * MATSZ);
    const int ko = grp << 4;
    FragA ah0, ah1, al0, al1;
    FragB bh0, bh1, bl0, bl1;
    wmma::load_matrix_sync(ah0, Ah + (wm * 32) * LDMAB + ko, LDMAB);
    wmma::load_matrix_sync(ah1, Ah + (wm * 32 + 16) * LDMAB + ko, LDMAB);
    wmma::load_matrix_sync(bh0, Bh + (wn * 32) * LDMAB + ko, LDMAB);
    wmma::load_matrix_sync(bh1, Bh + (wn * 32 + 16) * LDMAB + ko, LDMAB);
    wmma::mma_sync(c00, ah0, bh0, c00);
    wmma::mma_sync(c01, ah0, bh1, c01);
    wmma::mma_sync(c10, ah1, bh0, c10);
    wmma::mma_sync(c11, ah1, bh1, c11);
    wmma::load_matrix_sync(bl0, Bl + (wn * 32) * LDMAB + ko, LDMAB);
    wmma::load_matrix_sync(bl1, Bl + (wn * 32 + 16) * LDMAB + ko, LDMAB);
    wmma::mma_sync(c00, ah0, bl0, c00);
    wmma::mma_sync(c01, ah0, bl1, c01);
    wmma::mma_sync(c10, ah1, bl0, c10);
    wmma::mma_sync(c11, ah1, bl1, c11);
    wmma::load_matrix_sync(al0, Al + (wm * 32) * LDMAB + ko, LDMAB);
    wmma::load_matrix_sync(al1, Al + (wm * 32 + 16) * LDMAB + ko, LDMAB);
    wmma::mma_sync(c00, al0, bh0, c00);
    wmma::mma_sync(c01, al0, bh1, c01);
    wmma::mma_sync(c10, al1, bh0, c10);
    wmma::mma_sync(c11, al1, bh1, c11);
}

// ---------------- phase2 compute: warp tile 16x32, one kstep ----------------
static __device__ __forceinline__ void compute_p2(
    const char* buf, int grp, int wm, int wn, FragC& c0, FragC& c1) {
    const __nv_bfloat16* Ah = reinterpret_cast<const __nv_bfloat16*>(buf);
    const __nv_bfloat16* Al = reinterpret_cast<const __nv_bfloat16*>(buf + 4608);
    const __nv_bfloat16* Bh = reinterpret_cast<const __nv_bfloat16*>(buf + 9216);
    const __nv_bfloat16* Bl = reinterpret_cast<const __nv_bfloat16*>(buf + 9216 + MATSZ);
    const int ko = grp << 4;
    FragA ah, al;
    FragB bh0, bh1, bl0, bl1;
    wmma::load_matrix_sync(ah, Ah + (wm * 16) * LDMAB + ko, LDMAB);
    wmma::load_matrix_sync(bh0, Bh + (wn * 32) * LDMAB + ko, LDMAB);
    wmma::load_matrix_sync(bh1, Bh + (wn * 32 + 16) * LDMAB + ko, LDMAB);
    wmma::mma_sync(c0, ah, bh0, c0);
    wmma::mma_sync(c1, ah, bh1, c1);
    wmma::load_matrix_sync(bl0, Bl + (wn * 32) * LDMAB + ko, LDMAB);
    wmma::load_matrix_sync(bl1, Bl + (wn * 32 + 16) * LDMAB + ko, LDMAB);
    wmma::mma_sync(c0, ah, bl0, c0);
    wmma::mma_sync(c1, ah, bl1, c1);
    wmma::load_matrix_sync(al, Al + (wm * 16) * LDMAB + ko, LDMAB);
    wmma::mma_sync(c0, al, bh0, c0);
    wmma::mma_sync(c1, al, bh1, c1);
}

// ---------------- phase1 GEMM: 64x64x1024, 3-stage, issue-after-sync ------
static __device__ void run_gemm1(
    char* sm, uint32_t sbase,
    const __nv_bfloat16* __restrict__ ahi, const __nv_bfloat16* __restrict__ alo,
    const __nv_bfloat16* __restrict__ bhi, const __nv_bfloat16* __restrict__ blo,
    int tid, int grp, int wm, int wn) {
    FragC c00, c01, c10, c11;
    wmma::fill_fragment(c00, 0.f);
    wmma::fill_fragment(c01, 0.f);
    wmma::fill_fragment(c10, 0.f);
    wmma::fill_fragment(c11, 0.f);

    chunk1_A(sbase + 1024, ahi, alo, 0, tid);            CPCOMMIT();
    chunk1_A(sbase + 1024 + P1CH, ahi, alo, 128, tid);   CPCOMMIT();

#pragma unroll 1
    for (int c = 0; c < 8; ++c) {
        // wait for chunk c (outstanding after this: at most the newest group)
        if (c < 7) asm volatile("cp.async.wait_group 1;" ::: "memory");
        else       asm volatile("cp.async.wait_group 0;" ::: "memory");
        __syncthreads();   // all warps finished chunk c-1 (prev occupant of stage (c+2)%3)
        if (c + 2 <= 7) {  // RACE-FIX: issue AFTER the sync
            uint32_t sb = sbase + 1024 + ((c + 2) % 3) * P1CH;
            chunk1_A(sb, ahi, alo, (c + 2) * 128, tid);
            if (c + 2 >= 3) chunk1_B(sb, bhi, blo, (c + 2) * 128, tid);
            CPCOMMIT();
        }
        const char* buf = sm + 1024 + (c % 3) * P1CH;
        compute_p1(buf, grp, wm, wn, c00, c01, c10, c11);
        compute_p1(buf + P1SUB, grp, wm, wn, c00, c01, c10, c11);
    }
    // C partials alias stage0: last reader of stage0 was chunk 6, synced at iter 7
    float* sCg = reinterpret_cast<float*>(sm + CBASE) + grp * (64 * LDMC);
    wmma::store_matrix_sync(sCg + (wm * 32) * LDMC + wn * 32, c00, LDMC, wmma::mem_row_major);
    wmma::store_matrix_sync(sCg + (wm * 32) * LDMC + wn * 32 + 16, c01, LDMC, wmma::mem_row_major);
    wmma::store_matrix_sync(sCg + (wm * 32 + 16) * LDMC + wn * 32, c10, LDMC, wmma::mem_row_major);
    wmma::store_matrix_sync(sCg + (wm * 32 + 16) * LDMC + wn * 32 + 16, c11, LDMC, wmma::mem_row_major);
    __syncthreads();
}

// ---------------- phase2 GEMM: 32x64x1024, 3-stage, issue-after-sync ------
static __device__ void run_gemm2(
    char* sm, uint32_t sbase,
    const __nv_bfloat16* __restrict__ ahi, const __nv_bfloat16* __restrict__ alo,
    const __nv_bfloat16* __restrict__ bhi, const __nv_bfloat16* __restrict__ blo,
    int tid, int grp, int wm, int wn) {
    FragC c0, c1;
    wmma::fill_fragment(c0, 0.f);
    wmma::fill_fragment(c1, 0.f);

    chunk2_A(sbase + 1024, ahi, alo, 0, tid);            CPCOMMIT();
    chunk2_A(sbase + 1024 + P2CH, ahi, alo, 128, tid);   CPCOMMIT();

#pragma unroll 1
    for (int c = 0; c < 8; ++c) {
        if (c < 7) asm volatile("cp.async.wait_group 1;" ::: "memory");
        else       asm volatile("cp.async.wait_group 0;" ::: "memory");
        __syncthreads();
        if (c + 2 <= 7) {  // RACE-FIX: issue AFTER the sync
            uint32_t sb = sbase + 1024 + ((c + 2) % 3) * P2CH;
            chunk2_A(sb, ahi, alo, (c + 2) * 128, tid);
            if (c + 2 >= 3) chunk2_B(sb, bhi, blo, (c + 2) * 128, tid);
            CPCOMMIT();
        }
        const char* buf = sm + 1024 + (c % 3) * P2CH;
        compute_p2(buf, grp, wm, wn, c0, c1);
        compute_p2(buf + P2SUB, grp, wm, wn, c0, c1);
    }
    float* sCg = reinterpret_cast<float*>(sm + CBASE) + grp * (32 * LDMC);
    wmma::store_matrix_sync(sCg + (wm * 16) * LDMC + wn * 32, c0, LDMC, wmma::mem_row_major);
    wmma::store_matrix_sync(sCg + (wm * 16) * LDMC + wn * 32 + 16, c1, LDMC, wmma::mem_row_major);
    __syncthreads();
}

// ---------------- main persistent kernel ----------------
__global__ void __launch_bounds__(NTHR, 1)
gru_tc(const int* __restrict__ x,
       const float* __restrict__ Wph,
       const float* __restrict__ bp,
       float* __restrict__ out) {
    extern __shared__ __align__(16) char smem[];
    const uint32_t sbase = smem_u32(smem);
    const int tid = threadIdx.x;
    const int wid = tid >> 5;
    const int lane = tid & 31;
    const int cta = blockIdx.x;
    const int grp = wid >> 2;            // K group 0..3
    const int wpos = wid & 3;
    const int wm = wpos & 1, wn = wpos >> 1;

    for (int i = cta * NTHR + tid; i < BB * HH; i += NCTA * NTHR) {
        g_h[i] = 0.f;
        g_ha[0][i] = __float2bfloat16(0.f);
        g_ha[1][i] = __float2bfloat16(0.f);
    }

    // phase1: 128 tiles = 4 M-strips(64) x (16 z + 16 r) N-tiles(64)
    const int p1_bm = (cta & 3) << 6;
    const int p1_nt = cta >> 2;
    const int p1_gate = p1_nt >> 4;
    const int p1_jb = (p1_nt & 15) << 6;
    // phase2: 128 tiles = 8 M-strips(32) x 16 N-tiles(64)
    const int p2_bm = (cta & 7) << 5;
    const int p2_jb = (cta >> 3) << 6;

    const __nv_bfloat16* w1hi = &g_w[p1_gate][0][p1_jb * HH];
    const __nv_bfloat16* w1lo = &g_w[p1_gate][1][p1_jb * HH];
    const __nv_bfloat16* w2hi = &g_w[2][0][p2_jb * HH];
    const __nv_bfloat16* w2lo = &g_w[2][1][p2_jb * HH];

    preB1(sbase, w1hi, w1lo, tid);   // fill during init barrier
    grid_sync();

    const float* sC = reinterpret_cast<const float*>(smem + CBASE);

    for (int t = 0; t < TT; ++t) {
        // ============ phase 1: z / r gates ============
        run_gemm1(smem, sbase,
                  &g_ha[0][p1_bm * HH], &g_ha[1][p1_bm * HH],
                  w1hi, w1lo, tid, grp, wm, wn);
        {
            const int er = tid >> 3;              // 0..63
            const int ecb = (tid & 7) << 3;       // 8 cols
            const float* cr = sC + er * LDMC + ecb;
            float v[8];
            {
                float4 a0 = *reinterpret_cast<const float4*>(cr);
                float4 a1 = *reinterpret_cast<const float4*>(cr + 4);
#pragma unroll
                for (int g = 1; g < 4; ++g) {
                    const float* crg = cr + g * (64 * LDMC);
                    float4 b0 = *reinterpret_cast<const float4*>(crg);
                    float4 b1 = *reinterpret_cast<const float4*>(crg + 4);
                    a0.x += b0.x; a0.y += b0.y; a0.z += b0.z; a0.w += b0.w;
                    a1.x += b1.x; a1.y += b1.y; a1.z += b1.z; a1.w += b1.w;
                }
                v[0] = a0.x; v[1] = a0.y; v[2] = a0.z; v[3] = a0.w;
                v[4] = a1.x; v[5] = a1.y; v[6] = a1.z; v[7] = a1.w;
            }
            const int b = p1_bm + er;
            const int tok = x[b * TT + t];
            const float* __restrict__ pre = &g_pre[p1_gate][tok][p1_jb + ecb];
            if (p1_gate == 0) {
                float* __restrict__ dst = &g_z[b * HH + p1_jb + ecb];
#pragma unroll
                for (int q = 0; q < 2; ++q) {
                    float4 p = *reinterpret_cast<const float4*>(pre + q * 4);
                    float4 o;
                    o.x = sigf(v[q * 4 + 0] + p.x);
                    o.y = sigf(v[q * 4 + 1] + p.y);
                    o.z = sigf(v[q * 4 + 2] + p.z);
                    o.w = sigf(v[q * 4 + 3] + p.w);
                    *reinterpret_cast<float4*>(dst + q * 4) = o;
                }
            } else {
                const float* __restrict__ hrow = &g_h[b * HH + p1_jb + ecb];
                float hr[8];
#pragma unroll
                for (int q = 0; q < 2; ++q) {
                    float4 p = *reinterpret_cast<const float4*>(pre + q * 4);
                    float4 h4 = *reinterpret_cast<const float4*>(hrow + q * 4);
                    hr[q * 4 + 0] = sigf(v[q * 4 + 0] + p.x) * h4.x;
                    hr[q * 4 + 1] = sigf(v[q * 4 + 1] + p.y) * h4.y;
                    hr[q * 4 + 2] = sigf(v[q * 4 + 2] + p.z) * h4.z;
                    hr[q * 4 + 3] = sigf(v[q * 4 + 3] + p.w) * h4.w;
                }
                uint32_t phi[4], plo[4];
#pragma unroll
                for (int q = 0; q < 4; ++q) {
                    float a = hr[2 * q], bx = hr[2 * q + 1];
                    float ea = a - __bfloat162float(__float2bfloat16(a));
                    float eb = bx - __bfloat162float(__float2bfloat16(bx));
                    phi[q] = pack_bf2(a, bx);
                    plo[q] = pack_bf2(ea, eb);
                }
                *reinterpret_cast<uint4*>(&g_hra[0][b * HH + p1_jb + ecb]) =
                    make_uint4(phi[0], phi[1], phi[2], phi[3]);
                *reinterpret_cast<uint4*>(&g_hra[1][b * HH + p1_jb + ecb]) =
                    make_uint4(plo[0], plo[1], plo[2], plo[3]);
            }
        }
        __syncthreads();                  // epilogue C reads done before preB2 overwrite
        preB2(sbase, w2hi, w2lo, tid);    // fill during barrier wait
        grid_sync();

        // ============ phase 2: candidate + state update ============
        run_gemm2(smem, sbase,
                  &g_hra[0][p2_bm * HH], &g_hra[1][p2_bm * HH],
                  w2hi, w2lo, tid, grp, wm, wn);
        {
            const int er = tid >> 4;              // 0..31
            const int ecb = (tid & 15) << 2;      // 4 cols
            const float* cr = sC + er * LDMC + ecb;
            float4 v = *reinterpret_cast<const float4*>(cr);
#pragma unroll
            for (int g = 1; g < 4; ++g) {
                float4 bq = *reinterpret_cast<const float4*>(cr + g * (32 * LDMC));
                v.x += bq.x; v.y += bq.y; v.z += bq.z; v.w += bq.w;
            }
            const int b = p2_bm + er;
            const int tok = x[b * TT + t];
            const float* __restrict__ pre = &g_pre[2][tok][p2_jb + ecb];
            float* __restrict__ hrow = &g_h[b * HH + p2_jb + ecb];
            const float* __restrict__ zrow = &g_z[b * HH + p2_jb + ecb];
            float4 p = *reinterpret_cast<const float4*>(pre);
            float4 h4 = *reinterpret_cast<const float4*>(hrow);
            float4 z4 = *reinterpret_cast<const float4*>(zrow);
            float hn[4];
            hn[0] = h4.x + z4.x * (fast_tanh(v.x + p.x) - h4.x);
            hn[1] = h4.y + z4.y * (fast_tanh(v.y + p.y) - h4.y);
            hn[2] = h4.z + z4.z * (fast_tanh(v.z + p.z) - h4.z);
            hn[3] = h4.w + z4.w * (fast_tanh(v.w + p.w) - h4.w);
            *reinterpret_cast<float4*>(hrow) = make_float4(hn[0], hn[1], hn[2], hn[3]);
            uint32_t phi[2], plo[2];
#pragma unroll
            for (int q = 0; q < 2; ++q) {
                float a = hn[2 * q], bx = hn[2 * q + 1];
                float ea = a - __bfloat162float(__float2bfloat16(a));
                float eb = bx - __bfloat162float(__float2bfloat16(bx));
                phi[q] = pack_bf2(a, bx);
                plo[q] = pack_bf2(ea, eb);
            }
            *reinterpret_cast<uint2*>(&g_ha[0][b * HH + p2_jb + ecb]) = make_uint2(phi[0], phi[1]);
            *reinterpret_cast<uint2*>(&g_ha[1][b * HH + p2_jb + ecb]) = make_uint2(plo[0], plo[1]);
        }
        __syncthreads();
        preB1(sbase, w1hi, w1lo, tid);    // for next t (harmless at t=TT-1)
        grid_sync();
    }

    asm volatile("cp.async.wait_group 0;" ::: "memory");  // drain stray prefetch

    // ============ output projection ============
    const int warpId = (cta << 4) + wid;
    const int nWarps = NCTA << 4;
    for (int oc = warpId; oc < BB * CC; oc += nWarps) {
        const int b = oc / CC;
        const int c = oc - b * CC;
        const float* hrow = &g_h[b * HH];
        const float* wrow = &Wph[c * HH];
        float s = 0.f;
        for (int j = lane; j < HH; j += 32)
            s += hrow[j] * wrow[j];
#pragma unroll
        for (int off = 16; off; off >>= 1)
            s += __shfl_xor_sync(0xffffffffu, s, off);
        if (lane == 0) out[oc] = s + bp[c];
    }
}

// ---------------- launch ----------------
extern "C" void kernel_launch(void* const* d_in, const int* in_sizes, int n_in,
                              void* d_out, int out_size) {
    const int*   x     = (const int*)d_in[0];
    const float* embed = (const float*)d_in[1];
    const float* Wz    = (const float*)d_in[2];
    const float* Wr    = (const float*)d_in[3];
    const float* Wc    = (const float*)d_in[4];
    const float* Wph   = (const float*)d_in[5];
    const float* bp    = (const float*)d_in[6];
    float* out = (float*)d_out;

    cudaFuncSetAttribute(gru_tc, cudaFuncAttributeMaxDynamicSharedMemorySize, SMEM_TOTAL);

    const long total = 3L * HH * HH + 3L * VV * HH;
    precompute_kernel<<<(unsigned)((total + 255) / 256), 256>>>(embed, Wz, Wr, Wc);
    gru_tc<<<NCTA, NTHR, SMEM_TOTAL>>>(x, Wph, bp, out);
}